// round 4
// baseline (speedup 1.0000x reference)
#include <cuda_runtime.h>
#include <cstdint>

#define N_NODES   100000
#define N_EDGES   1200000
#define NODE_DIM  64
#define NUM_LAYERS 3
#define NUM_GRAPHS 256
#define R_HID     128
#define R_OUT     32

#define NN (N_NODES * NODE_DIM)

// Scratch (allocation-free rule: __device__ globals)
__device__ float g_agg[NN];                    // neighbor-sum buffer
__device__ float g_h[NUM_LAYERS][NN];          // per-layer GIN outputs
__device__ float g_pool[NUM_GRAPHS * NUM_LAYERS * NODE_DIM];  // pooled [B,192]

// ---------------------------------------------------------------------------
// Edge aggregation: agg[dst] += h[src], 64 floats per edge.
// 16 threads per edge, each owns one float4 -> warp gather = 2 coalesced
// 256B rows. Scatter via vector red.global.add.v4.f32 (no return, L2 atomics).
// ---------------------------------------------------------------------------
__global__ void __launch_bounds__(256)
edge_kernel(const float4* __restrict__ h,
            const int* __restrict__ src,
            const int* __restrict__ dst,
            float4* __restrict__ agg)
{
    unsigned idx = blockIdx.x * 256u + threadIdx.x;
    unsigned e = idx >> 4;
    if (e >= N_EDGES) return;
    unsigned lane = idx & 15u;
    int s = __ldg(&src[e]);
    int d = __ldg(&dst[e]);
    float4 v = __ldg(&h[(unsigned)s * 16u + lane]);
    float4* p = &agg[(unsigned)d * 16u + lane];
    asm volatile("red.global.add.v4.f32 [%0], {%1,%2,%3,%4};"
                 :: "l"(p), "f"(v.x), "f"(v.y), "f"(v.z), "f"(v.w)
                 : "memory");
}

// ---------------------------------------------------------------------------
// GIN layer: h_out = relu(((1+eps)*h_in + agg) @ W + b)
// 128 threads/block, 1 node/thread, 128-node tile.
// Input tile staged through padded smem (pitch 65 -> conflict-free), W in smem
// read as broadcast float4 (1 LDS.128 per 4 FFMA). Output staged back through
// smem for coalesced global stores.
// Dynamic smem: W(16384) + b(256) + tile(128*65*4=33280) = 49920 B.
// ---------------------------------------------------------------------------
__global__ void __launch_bounds__(128)
gin_kernel(const float* __restrict__ h_in,
           const float* __restrict__ agg,
           const float* __restrict__ W,
           const float* __restrict__ b,
           const float* __restrict__ eps_l,
           float* __restrict__ h_out)
{
    extern __shared__ float sm[];
    float* sW = sm;            // [64*64]
    float* sB = sm + 64 * 64;  // [64]
    float* sT = sB + 64;       // [128][65]

    const int tid = threadIdx.x;
    const int nodeBase = blockIdx.x * 128;
    const float eps1 = 1.0f + __ldg(eps_l);

    for (int i = tid; i < 64 * 64; i += 128) sW[i] = __ldg(&W[i]);
    if (tid < 64) sB[tid] = __ldg(&b[tid]);

    // cooperative coalesced load of combined input
    for (int i = tid; i < 128 * 64; i += 128) {
        int node = nodeBase + (i >> 6);
        int dcol = i & 63;
        float v = 0.0f;
        if (node < N_NODES) {
            int gi = node * 64 + dcol;
            v = eps1 * __ldg(&h_in[gi]) + __ldg(&agg[gi]);
        }
        sT[(i >> 6) * 65 + dcol] = v;
    }
    __syncthreads();

    // pull my row into registers
    float hin[64];
    #pragma unroll
    for (int k = 0; k < 64; k++) hin[k] = sT[tid * 65 + k];

    const float4* sW4 = reinterpret_cast<const float4*>(sW);

    for (int j = 0; j < 64; j += 4) {
        float4 acc;
        acc.x = sB[j + 0]; acc.y = sB[j + 1];
        acc.z = sB[j + 2]; acc.w = sB[j + 3];
        int j4 = j >> 2;
        #pragma unroll
        for (int k = 0; k < 64; k++) {
            float hv = hin[k];
            float4 w = sW4[k * 16 + j4];        // broadcast LDS.128
            acc.x = fmaf(hv, w.x, acc.x);
            acc.y = fmaf(hv, w.y, acc.y);
            acc.z = fmaf(hv, w.z, acc.z);
            acc.w = fmaf(hv, w.w, acc.w);
        }
        // per-thread private row: safe to overwrite without extra sync
        sT[tid * 65 + j + 0] = fmaxf(acc.x, 0.0f);
        sT[tid * 65 + j + 1] = fmaxf(acc.y, 0.0f);
        sT[tid * 65 + j + 2] = fmaxf(acc.z, 0.0f);
        sT[tid * 65 + j + 3] = fmaxf(acc.w, 0.0f);
    }
    __syncthreads();

    // cooperative coalesced writeout
    for (int i = tid; i < 128 * 64; i += 128) {
        int node = nodeBase + (i >> 6);
        if (node < N_NODES)
            h_out[node * 64 + (i & 63)] = sT[(i >> 6) * 65 + (i & 63)];
    }
}

// ---------------------------------------------------------------------------
// Graph pooling: g[b, l*64+d] = sum over nodes of graph b of g_h[l][node][d]
// graph_ids are sorted -> binary search for [start,end). No atomics.
// 256 blocks (one per graph) x 192 threads (one per output dim).
// ---------------------------------------------------------------------------
__global__ void __launch_bounds__(192)
pool_kernel(const int* __restrict__ gids)
{
    const int b = blockIdx.x;
    const int j = threadIdx.x;

    int lo = 0, hi = N_NODES;
    while (lo < hi) { int m = (lo + hi) >> 1; if (__ldg(&gids[m]) < b) lo = m + 1; else hi = m; }
    const int start = lo;
    hi = N_NODES;
    while (lo < hi) { int m = (lo + hi) >> 1; if (__ldg(&gids[m]) < b + 1) lo = m + 1; else hi = m; }
    const int end = lo;

    const int l = j >> 6;
    const int d = j & 63;
    const float* __restrict__ hb = g_h[l];

    float a0 = 0.f, a1 = 0.f, a2 = 0.f, a3 = 0.f;
    int n = start;
    for (; n + 3 < end; n += 4) {
        a0 += __ldg(&hb[(n + 0) * 64 + d]);
        a1 += __ldg(&hb[(n + 1) * 64 + d]);
        a2 += __ldg(&hb[(n + 2) * 64 + d]);
        a3 += __ldg(&hb[(n + 3) * 64 + d]);
    }
    for (; n < end; n++) a0 += __ldg(&hb[n * 64 + d]);
    g_pool[b * (NUM_LAYERS * NODE_DIM) + j] = (a0 + a1) + (a2 + a3);
}

// ---------------------------------------------------------------------------
// Readout MLP: out = relu(g @ W1 + b1) @ W2 + b2
// 256 blocks (one per graph) x 128 threads (one per hidden unit).
// ---------------------------------------------------------------------------
__global__ void __launch_bounds__(128)
readout_kernel(const float* __restrict__ W1, const float* __restrict__ b1,
               const float* __restrict__ W2, const float* __restrict__ b2,
               float* __restrict__ out)
{
    const int b = blockIdx.x;
    const int tid = threadIdx.x;
    __shared__ float sg[NUM_LAYERS * NODE_DIM];  // 192
    __shared__ float sh[R_HID];                  // 128

    for (int i = tid; i < NUM_LAYERS * NODE_DIM; i += 128)
        sg[i] = g_pool[b * (NUM_LAYERS * NODE_DIM) + i];
    __syncthreads();

    float acc = __ldg(&b1[tid]);
    #pragma unroll 8
    for (int k = 0; k < NUM_LAYERS * NODE_DIM; k++)
        acc = fmaf(sg[k], __ldg(&W1[k * R_HID + tid]), acc);
    sh[tid] = fmaxf(acc, 0.0f);
    __syncthreads();

    if (tid < R_OUT) {
        float o = __ldg(&b2[tid]);
        #pragma unroll 8
        for (int k = 0; k < R_HID; k++)
            o = fmaf(sh[k], __ldg(&W2[k * R_OUT + tid]), o);
        out[b * R_OUT + tid] = o;
    }
}

// ---------------------------------------------------------------------------
extern "C" void kernel_launch(void* const* d_in, const int* in_sizes, int n_in,
                              void* d_out, int out_size)
{
    const float* x     = (const float*)d_in[0];
    const float* gin_W = (const float*)d_in[1];
    const float* gin_b = (const float*)d_in[2];
    const float* eps   = (const float*)d_in[3];
    const float* r_W1  = (const float*)d_in[4];
    const float* r_b1  = (const float*)d_in[5];
    const float* r_W2  = (const float*)d_in[6];
    const float* r_b2  = (const float*)d_in[7];
    const int*   src   = (const int*)d_in[8];
    const int*   dst   = (const int*)d_in[9];
    const int*   gids  = (const int*)d_in[10];
    float* out = (float*)d_out;

    void* aggp = nullptr;
    void* hsym = nullptr;
    cudaGetSymbolAddress(&aggp, g_agg);
    cudaGetSymbolAddress(&hsym, g_h);
    float* hbase = (float*)hsym;

    const int GIN_SMEM = (64 * 64 + 64 + 128 * 65) * (int)sizeof(float);  // 49920 B
    cudaFuncSetAttribute(gin_kernel, cudaFuncAttributeMaxDynamicSharedMemorySize, GIN_SMEM);

    const int EDGE_BLOCKS = (N_EDGES * 16 + 255) / 256;   // 75000
    const int GIN_BLOCKS  = (N_NODES + 127) / 128;        // 782

    for (int l = 0; l < NUM_LAYERS; l++) {
        const float* hin = (l == 0) ? x : (hbase + (size_t)(l - 1) * NN);
        cudaMemsetAsync(aggp, 0, (size_t)NN * sizeof(float));
        edge_kernel<<<EDGE_BLOCKS, 256>>>((const float4*)hin, src, dst, (float4*)aggp);
        gin_kernel<<<GIN_BLOCKS, 128, GIN_SMEM>>>(hin, (const float*)aggp,
                                                  gin_W + (size_t)l * 64 * 64,
                                                  gin_b + (size_t)l * 64,
                                                  eps + l,
                                                  hbase + (size_t)l * NN);
    }
    pool_kernel<<<NUM_GRAPHS, NUM_LAYERS * NODE_DIM>>>(gids);
    readout_kernel<<<NUM_GRAPHS, R_HID>>>(r_W1, r_b1, r_W2, r_b2, out);
}